// round 3
// baseline (speedup 1.0000x reference)
#include <cuda_runtime.h>

// Problem constants (fixed by the dataset)
#define NN 50000
#define LL 4
#define EE 1600000
#define CC 128
#define NM 8          // 8 sparse matrices: m<4 -> phi_inverse[l], m>=4 -> phi[l-4]

// ----------------------------------------------------------------------------
// Scratch (static device globals; allocation-free per harness rules)
// ----------------------------------------------------------------------------
__device__ int   g_rowptr[NM][NN + 1];                 // CSR row pointers
__device__ int   g_cnt[NM][NN];                        // histogram / cursors
__device__ int   g_scol[(size_t)NM * EE];              // CSR cols (row-sorted)
__device__ float g_sval[(size_t)NM * EE];              // CSR vals (row-sorted)
__device__ __align__(16) float g_Y1[(size_t)LL * NN * CC];  // feats @ W, [l][n][c]
__device__ __align__(16) float g_Y2[(size_t)LL * NN * CC];  // theta * (phi_inv @ Y1)

// ----------------------------------------------------------------------------
// 1) zero the per-row counters
// ----------------------------------------------------------------------------
__global__ void zero_cnt_kernel() {
    int i = blockIdx.x * blockDim.x + threadIdx.x;
    if (i < NM * NN) ((int*)g_cnt)[i] = 0;
}

// ----------------------------------------------------------------------------
// 2) histogram of row indices  (grid: x = EE/256, y = NM)
// ----------------------------------------------------------------------------
__global__ void hist_kernel(const int* __restrict__ phi_idx,
                            const int* __restrict__ inv_idx) {
    int e = blockIdx.x * blockDim.x + threadIdx.x;
    int m = blockIdx.y;
    const int* rows = (m < LL) ? (inv_idx + (size_t)m * 2 * EE)
                               : (phi_idx + (size_t)(m - LL) * 2 * EE);
    atomicAdd(&g_cnt[m][rows[e]], 1);
}

// ----------------------------------------------------------------------------
// 3) exclusive scan per matrix -> rowptr; resets cnt to 0 for the scatter pass
//    one block (1024 threads) per matrix, chunked Hillis-Steele
// ----------------------------------------------------------------------------
__global__ void scan_kernel() {
    __shared__ int sh[1024];
    __shared__ int s_carry;
    int m = blockIdx.x;
    int tid = threadIdx.x;
    if (tid == 0) { s_carry = 0; g_rowptr[m][0] = 0; }
    __syncthreads();
    for (int base = 0; base < NN; base += 1024) {
        int i = base + tid;
        int v = (i < NN) ? g_cnt[m][i] : 0;
        sh[tid] = v;
        __syncthreads();
        for (int off = 1; off < 1024; off <<= 1) {
            int add = (tid >= off) ? sh[tid - off] : 0;
            __syncthreads();
            sh[tid] += add;
            __syncthreads();
        }
        int incl = sh[tid];
        if (i < NN) {
            g_rowptr[m][i + 1] = s_carry + incl;
            g_cnt[m][i] = 0;
        }
        __syncthreads();                 // everyone read s_carry
        if (tid == 1023) s_carry += sh[1023];
        __syncthreads();
    }
}

// ----------------------------------------------------------------------------
// 4) scatter edges into row-sorted CSR arrays  (grid: x = EE/256, y = NM)
// ----------------------------------------------------------------------------
__global__ void scatter_kernel(const int* __restrict__ phi_idx,
                               const float* __restrict__ phi_val,
                               const int* __restrict__ inv_idx,
                               const float* __restrict__ inv_val) {
    int e = blockIdx.x * blockDim.x + threadIdx.x;
    int m = blockIdx.y;
    const int*   base = (m < LL) ? (inv_idx + (size_t)m * 2 * EE)
                                 : (phi_idx + (size_t)(m - LL) * 2 * EE);
    const float* vals = (m < LL) ? (inv_val + (size_t)m * EE)
                                 : (phi_val + (size_t)(m - LL) * EE);
    int   r = base[e];
    int   c = base[EE + e];
    float v = vals[e];
    int pos = g_rowptr[m][r] + atomicAdd(&g_cnt[m][r], 1);
    g_scol[(size_t)m * EE + pos] = c;
    g_sval[(size_t)m * EE + pos] = v;
}

// ----------------------------------------------------------------------------
// 5) GEMM: Y1[l][n][:] = features[n][l][:] @ W   (W staged in smem, 2 halves)
//    128 threads (c = tid), 16 rows per block
// ----------------------------------------------------------------------------
#define GEMM_R 16
__global__ void gemm_kernel(const float* __restrict__ feats,
                            const float* __restrict__ W) {
    __shared__ __align__(16) float Ws[64 * CC];      // 32 KB half of W
    __shared__ __align__(16) float Fs[GEMM_R * CC];  // 8 KB feature tile
    int tid = threadIdx.x;     // output column c
    int row0 = blockIdx.x * GEMM_R;   // row index t in [0, LL*NN), t = l*NN + n

    // load feature tile (transposed gather from [n][l][c] layout)
    #pragma unroll
    for (int rr = 0; rr < GEMM_R; rr++) {
        int t = row0 + rr;
        int l = t / NN;
        int n = t - l * NN;
        Fs[rr * CC + tid] = feats[((size_t)n * LL + l) * CC + tid];
    }

    float acc[GEMM_R];
    #pragma unroll
    for (int rr = 0; rr < GEMM_R; rr++) acc[rr] = 0.f;

    for (int h = 0; h < 2; h++) {
        __syncthreads();
        // stage half of W: rows [h*64, h*64+64)
        #pragma unroll
        for (int i = tid; i < 64 * CC; i += 128) Ws[i] = W[(size_t)h * 64 * CC + i];
        __syncthreads();

        #pragma unroll 4
        for (int k = 0; k < 64; k += 4) {
            float w0 = Ws[(k + 0) * CC + tid];
            float w1 = Ws[(k + 1) * CC + tid];
            float w2 = Ws[(k + 2) * CC + tid];
            float w3 = Ws[(k + 3) * CC + tid];
            #pragma unroll
            for (int rr = 0; rr < GEMM_R; rr++) {
                float4 f = *(const float4*)&Fs[rr * CC + h * 64 + k];
                acc[rr] = fmaf(f.x, w0, acc[rr]);
                acc[rr] = fmaf(f.y, w1, acc[rr]);
                acc[rr] = fmaf(f.z, w2, acc[rr]);
                acc[rr] = fmaf(f.w, w3, acc[rr]);
            }
        }
    }

    #pragma unroll
    for (int rr = 0; rr < GEMM_R; rr++) {
        int t = row0 + rr;
        int l = t / NN;
        int n = t - l * NN;
        g_Y1[(size_t)l * NN * CC + (size_t)n * CC + tid] = acc[rr];
    }
}

// ----------------------------------------------------------------------------
// 6) SpMM stage 1: Y2[l] = theta .* (phi_inv[l] @ Y1[l])
//    warp per output row; each lane owns 4 consecutive channels (float4)
// ----------------------------------------------------------------------------
__global__ void spmm_inv_kernel(const float* __restrict__ theta) {
    int wg   = (blockIdx.x * blockDim.x + threadIdx.x) >> 5;  // [0, LL*NN)
    int lane = threadIdx.x & 31;
    int l = wg / NN;
    int r = wg - l * NN;
    int m = l;                                // phi_inverse matrices
    int start = g_rowptr[m][r];
    int end   = g_rowptr[m][r + 1];
    const float4* Xv = (const float4*)(g_Y1 + (size_t)l * NN * CC);
    const int*    sc = g_scol + (size_t)m * EE;
    const float*  sv = g_sval + (size_t)m * EE;

    float4 acc = make_float4(0.f, 0.f, 0.f, 0.f);
    for (int e0 = start; e0 < end; e0 += 32) {
        int   me = e0 + lane;
        int   c_ = (me < end) ? sc[me] : 0;
        float v_ = (me < end) ? sv[me] : 0.f;
        int cnt = min(32, end - e0);
        #pragma unroll 4
        for (int j = 0; j < cnt; j++) {
            int   col = __shfl_sync(0xffffffffu, c_, j);
            float val = __shfl_sync(0xffffffffu, v_, j);
            float4 x = Xv[col * 32 + lane];
            acc.x = fmaf(val, x.x, acc.x);
            acc.y = fmaf(val, x.y, acc.y);
            acc.z = fmaf(val, x.z, acc.z);
            acc.w = fmaf(val, x.w, acc.w);
        }
    }
    float t = theta[r];
    acc.x *= t; acc.y *= t; acc.z *= t; acc.w *= t;
    float4* out = (float4*)(g_Y2 + (size_t)l * NN * CC);
    out[r * 32 + lane] = acc;
}

// ----------------------------------------------------------------------------
// 7) SpMM stage 2: out[n][l][:] = phi[l] @ Y2[l]
// ----------------------------------------------------------------------------
__global__ void spmm_phi_kernel(float* __restrict__ outp) {
    int wg   = (blockIdx.x * blockDim.x + threadIdx.x) >> 5;
    int lane = threadIdx.x & 31;
    int l = wg / NN;
    int r = wg - l * NN;
    int m = LL + l;                           // phi matrices
    int start = g_rowptr[m][r];
    int end   = g_rowptr[m][r + 1];
    const float4* Xv = (const float4*)(g_Y2 + (size_t)l * NN * CC);
    const int*    sc = g_scol + (size_t)m * EE;
    const float*  sv = g_sval + (size_t)m * EE;

    float4 acc = make_float4(0.f, 0.f, 0.f, 0.f);
    for (int e0 = start; e0 < end; e0 += 32) {
        int   me = e0 + lane;
        int   c_ = (me < end) ? sc[me] : 0;
        float v_ = (me < end) ? sv[me] : 0.f;
        int cnt = min(32, end - e0);
        #pragma unroll 4
        for (int j = 0; j < cnt; j++) {
            int   col = __shfl_sync(0xffffffffu, c_, j);
            float val = __shfl_sync(0xffffffffu, v_, j);
            float4 x = Xv[col * 32 + lane];
            acc.x = fmaf(val, x.x, acc.x);
            acc.y = fmaf(val, x.y, acc.y);
            acc.z = fmaf(val, x.z, acc.z);
            acc.w = fmaf(val, x.w, acc.w);
        }
    }
    // output layout [n][l][c]
    float4* out = (float4*)outp;
    out[(r * LL + l) * 32 + lane] = acc;
}

// ----------------------------------------------------------------------------
// launch
// ----------------------------------------------------------------------------
extern "C" void kernel_launch(void* const* d_in, const int* in_sizes, int n_in,
                              void* d_out, int out_size) {
    const int*   phi_idx = (const int*)d_in[0];    // [L,2,E]
    const float* phi_val = (const float*)d_in[1];  // [L,E]
    const int*   inv_idx = (const int*)d_in[2];    // [L,2,E]
    const float* inv_val = (const float*)d_in[3];  // [L,E]
    const float* feats   = (const float*)d_in[4];  // [N,L,C]
    const float* W       = (const float*)d_in[5];  // [C,C]
    const float* theta   = (const float*)d_in[6];  // [N]
    float*       outp    = (float*)d_out;          // [N,L,C]

    // CSR build (every launch; graph-replayed)
    zero_cnt_kernel<<<(NM * NN + 255) / 256, 256>>>();
    dim3 gE(EE / 256, NM);
    hist_kernel<<<gE, 256>>>(phi_idx, inv_idx);
    scan_kernel<<<NM, 1024>>>();
    scatter_kernel<<<gE, 256>>>(phi_idx, phi_val, inv_idx, inv_val);

    // dense GEMM: Y1 = feats @ W (per scale)
    gemm_kernel<<<(LL * NN) / GEMM_R, 128>>>(feats, W);

    // SpMM stages (warp per row, 8 warps per block)
    spmm_inv_kernel<<<(LL * NN) / 8, 256>>>(theta);
    spmm_phi_kernel<<<(LL * NN) / 8, 256>>>(outp);
}